// round 1
// baseline (speedup 1.0000x reference)
#include <cuda_runtime.h>
#include <cuda_bf16.h>

#define M_SZ   100
#define H_SZ   256
#define W_SZ   512
#define N_INST 64
#define C_THING 80
#define C_STUFF 53

// One block per (row y, instance n). 128 threads * float4 covers W=512.
__global__ void panoptic_thing_kernel(const float* __restrict__ mask_logits,   // [N, C_THING, M, M]
                                      const float* __restrict__ sem_seg,       // [1, C_STUFF+C_THING, H, W]
                                      const float* __restrict__ bbox,          // [N, 4]
                                      const int*   __restrict__ cls_idx,       // [N]
                                      float* __restrict__ out)                 // [1, C_STUFF+N, H, W]
{
    const int n  = blockIdx.z;
    const int y  = blockIdx.y;
    const int x0 = threadIdx.x * 4;

    const float bx1 = __ldg(&bbox[n * 4 + 0]);
    const float by1 = __ldg(&bbox[n * 4 + 1]);
    const float bx2 = __ldg(&bbox[n * 4 + 2]);
    const float by2 = __ldg(&bbox[n * 4 + 3]);
    const int   cls = __ldg(&cls_idx[n]);

    // ---- paste (bilinear resize of mask into floor-box) ----
    const int x1b = (int)floorf(bx1);
    const int y1b = (int)floorf(by1);
    const int x2b = (int)floorf(bx2);
    const int y2b = (int)floorf(by2);
    const float bwf = (float)(x2b - x1b + 1);
    const float bhf = (float)(y2b - y1b + 1);

    const float* __restrict__ mtile =
        mask_logits + ((size_t)n * C_THING + (size_t)cls) * (M_SZ * M_SZ);

    float vals[4] = {0.f, 0.f, 0.f, 0.f};

    const bool row_in_paste = (y >= max(y1b, 0)) && (y < min(y2b + 1, H_SZ));
    if (row_in_paste) {
        float my = ((float)y - (float)y1b + 0.5f) * ((float)M_SZ / bhf) - 0.5f;
        my = fmaxf(my, 0.f);
        const float myf = floorf(my);
        const float fy  = my - myf;
        const int iy0 = min((int)myf,     M_SZ - 1);
        const int iy1 = min((int)myf + 1, M_SZ - 1);
        const float* __restrict__ mrow0 = mtile + iy0 * M_SZ;
        const float* __restrict__ mrow1 = mtile + iy1 * M_SZ;

        const int xlo = max(x1b, 0);
        const int xhi = min(x2b + 1, W_SZ);
        #pragma unroll
        for (int j = 0; j < 4; ++j) {
            const int x = x0 + j;
            if (x >= xlo && x < xhi) {
                float mx = ((float)x - (float)x1b + 0.5f) * ((float)M_SZ / bwf) - 0.5f;
                mx = fmaxf(mx, 0.f);
                const float mxf = floorf(mx);
                const float fx  = mx - mxf;
                const int ix0 = min((int)mxf,     M_SZ - 1);
                const int ix1 = min((int)mxf + 1, M_SZ - 1);
                const float top = mrow0[ix0] * (1.f - fx) + mrow0[ix1] * fx;
                const float bot = mrow1[ix0] * (1.f - fx) + mrow1[ix1] * fx;
                vals[j] = (1.f - fy) * top + fy * bot;
            }
        }
    }

    // ---- crop (thing sem-seg channel inside trunc/round box) ----
    const int cx1 = (int)bx1;                 // truncation (coords >= 0, same as floor)
    const int cy1 = (int)by1;
    const int cx2 = (int)rintf(bx2) + 1;      // jnp.round = round-half-even
    const int cy2 = (int)rintf(by2) + 1;
    if (y >= cy1 && y < cy2) {
        const float* __restrict__ srow =
            sem_seg + ((size_t)(C_STUFF + cls) * H_SZ + (size_t)y) * W_SZ;
        #pragma unroll
        for (int j = 0; j < 4; ++j) {
            const int x = x0 + j;
            if (x >= cx1 && x < cx2) vals[j] += __ldg(&srow[x]);
        }
    }

    float4* __restrict__ orow =
        (float4*)(out + ((size_t)(C_STUFF + n) * H_SZ + (size_t)y) * W_SZ + x0);
    *orow = make_float4(vals[0], vals[1], vals[2], vals[3]);
}

extern "C" void kernel_launch(void* const* d_in, const int* in_sizes, int n_in,
                              void* d_out, int out_size)
{
    const float* mask_logits = (const float*)d_in[0];
    const float* sem_seg     = (const float*)d_in[1];
    const float* bbox        = (const float*)d_in[2];
    const int*   cls_idx     = (const int*)d_in[3];
    float*       out         = (float*)d_out;

    // Stuff channels: straight copy of the first 53 channels (contiguous prefix).
    cudaMemcpyAsync(out, sem_seg,
                    (size_t)C_STUFF * H_SZ * W_SZ * sizeof(float),
                    cudaMemcpyDeviceToDevice, 0);

    // Thing channels: paste + crop, zeros elsewhere.
    dim3 grid(1, H_SZ, N_INST);
    panoptic_thing_kernel<<<grid, 128>>>(mask_logits, sem_seg, bbox, cls_idx, out);
}

// round 2
// speedup vs baseline: 1.0915x; 1.0915x over previous
#include <cuda_runtime.h>
#include <cuda_bf16.h>

#define M_SZ    100
#define H_SZ    256
#define W_SZ    512
#define N_INST  64
#define C_THING 80
#define C_STUFF 53
#define C_OUT   (C_STUFF + N_INST)   // 117
#define ROWS_PB 4

// Block = (128, 4): 128 threads * float4 = one 512-wide row, 4 rows per block.
// Grid covers all C_OUT * H rows. Channels < C_STUFF: straight copy.
// Channels >= C_STUFF: paste(bilinear mask) + crop(thing sem channel), zero outside.
__global__ __launch_bounds__(512)
void panoptic_all_kernel(const float* __restrict__ mask_logits,   // [N, C_THING, M, M]
                         const float* __restrict__ sem_seg,       // [1, C_STUFF+C_THING, H, W]
                         const float* __restrict__ bbox,          // [N, 4]
                         const int*   __restrict__ cls_idx,       // [N]
                         float* __restrict__ out)                 // [1, C_OUT, H, W]
{
    const int grow = blockIdx.x * ROWS_PB + threadIdx.y;   // global row in [0, C_OUT*H)
    const int c    = grow >> 8;                             // H == 256
    const int y    = grow & (H_SZ - 1);
    const int x0   = threadIdx.x * 4;

    float4* __restrict__ orow =
        (float4*)(out + ((size_t)c * H_SZ + (size_t)y) * W_SZ + x0);

    if (c < C_STUFF) {
        // stuff channel: verbatim copy (same channel index in sem_seg)
        *orow = *(const float4*)(sem_seg + ((size_t)c * H_SZ + (size_t)y) * W_SZ + x0);
        return;
    }

    const int n = c - C_STUFF;

    const float bx1 = __ldg(&bbox[n * 4 + 0]);
    const float by1 = __ldg(&bbox[n * 4 + 1]);
    const float bx2 = __ldg(&bbox[n * 4 + 2]);
    const float by2 = __ldg(&bbox[n * 4 + 3]);
    const int   cls = __ldg(&cls_idx[n]);

    // ---- paste (bilinear resize of mask into floor-box) ----
    const int x1b = (int)floorf(bx1);
    const int y1b = (int)floorf(by1);
    const int x2b = (int)floorf(bx2);
    const int y2b = (int)floorf(by2);

    float vals[4] = {0.f, 0.f, 0.f, 0.f};

    const bool row_in_paste = (y >= max(y1b, 0)) && (y < min(y2b + 1, H_SZ));
    if (row_in_paste) {
        const float bwf = (float)(x2b - x1b + 1);
        const float bhf = (float)(y2b - y1b + 1);
        const float* __restrict__ mtile =
            mask_logits + ((size_t)n * C_THING + (size_t)cls) * (M_SZ * M_SZ);

        float my = ((float)y - (float)y1b + 0.5f) * ((float)M_SZ / bhf) - 0.5f;
        my = fmaxf(my, 0.f);
        const float myf = floorf(my);
        const float fy  = my - myf;
        const int iy0 = min((int)myf,     M_SZ - 1);
        const int iy1 = min((int)myf + 1, M_SZ - 1);
        const float* __restrict__ mrow0 = mtile + iy0 * M_SZ;
        const float* __restrict__ mrow1 = mtile + iy1 * M_SZ;

        const int xlo = max(x1b, 0);
        const int xhi = min(x2b + 1, W_SZ);
        const float invbw = (float)M_SZ / bwf;
        #pragma unroll
        for (int j = 0; j < 4; ++j) {
            const int x = x0 + j;
            if (x >= xlo && x < xhi) {
                float mx = ((float)x - (float)x1b + 0.5f) * invbw - 0.5f;
                mx = fmaxf(mx, 0.f);
                const float mxf = floorf(mx);
                const float fx  = mx - mxf;
                const int ix0 = min((int)mxf,     M_SZ - 1);
                const int ix1 = min((int)mxf + 1, M_SZ - 1);
                const float top = mrow0[ix0] * (1.f - fx) + mrow0[ix1] * fx;
                const float bot = mrow1[ix0] * (1.f - fx) + mrow1[ix1] * fx;
                vals[j] = (1.f - fy) * top + fy * bot;
            }
        }
    }

    // ---- crop (thing sem-seg channel inside trunc/round box) ----
    const int cy1 = (int)by1;                 // truncation (coords >= 0)
    const int cy2 = (int)rintf(by2) + 1;      // jnp.round = round-half-even
    if (y >= cy1 && y < cy2) {
        const int cx1 = (int)bx1;
        const int cx2 = (int)rintf(bx2) + 1;
        const float* __restrict__ srow =
            sem_seg + ((size_t)(C_STUFF + cls) * H_SZ + (size_t)y) * W_SZ;
        #pragma unroll
        for (int j = 0; j < 4; ++j) {
            const int x = x0 + j;
            if (x >= cx1 && x < cx2) vals[j] += __ldg(&srow[x]);
        }
    }

    *orow = make_float4(vals[0], vals[1], vals[2], vals[3]);
}

extern "C" void kernel_launch(void* const* d_in, const int* in_sizes, int n_in,
                              void* d_out, int out_size)
{
    const float* mask_logits = (const float*)d_in[0];
    const float* sem_seg     = (const float*)d_in[1];
    const float* bbox        = (const float*)d_in[2];
    const int*   cls_idx     = (const int*)d_in[3];
    float*       out         = (float*)d_out;

    const int total_rows = C_OUT * H_SZ;                 // 29952
    dim3 block(128, ROWS_PB);
    dim3 grid(total_rows / ROWS_PB);                     // 7488
    panoptic_all_kernel<<<grid, block>>>(mask_logits, sem_seg, bbox, cls_idx, out);
}

// round 3
// speedup vs baseline: 1.3561x; 1.2424x over previous
#include <cuda_runtime.h>
#include <cuda_bf16.h>

#define M_SZ    100
#define H_SZ    256
#define W_SZ    512
#define N_INST  64
#define C_THING 80
#define C_STUFF 53
#define C_OUT   (C_STUFF + N_INST)   // 117
#define WARPS_PB 8

// One warp per output row (512 floats = 128 float4). Lane l handles float4
// columns l, l+32, l+64, l+96  -> 4 independent ld/st per thread (MLP=4).
__global__ __launch_bounds__(WARPS_PB * 32)
void panoptic_all_kernel(const float* __restrict__ mask_logits,   // [N, C_THING, M, M]
                         const float* __restrict__ sem_seg,       // [1, C_STUFF+C_THING, H, W]
                         const float* __restrict__ bbox,          // [N, 4]
                         const int*   __restrict__ cls_idx,       // [N]
                         float* __restrict__ out)                 // [1, C_OUT, H, W]
{
    const int warp = threadIdx.x >> 5;
    const int lane = threadIdx.x & 31;
    const int grow = blockIdx.x * WARPS_PB + warp;          // row in [0, C_OUT*H)
    const int c    = grow >> 8;                              // H == 256
    const int y    = grow & (H_SZ - 1);

    float4* __restrict__ orow = (float4*)(out + (size_t)grow * W_SZ);

    if (c < C_STUFF) {
        // stuff channel: verbatim copy, 4 independent 16B loads then 4 stores
        const float4* __restrict__ srow =
            (const float4*)(sem_seg + (size_t)grow * W_SZ);
        float4 v0 = srow[lane];
        float4 v1 = srow[lane + 32];
        float4 v2 = srow[lane + 64];
        float4 v3 = srow[lane + 96];
        orow[lane]      = v0;
        orow[lane + 32] = v1;
        orow[lane + 64] = v2;
        orow[lane + 96] = v3;
        return;
    }

    const int n = c - C_STUFF;

    const float bx1 = __ldg(&bbox[n * 4 + 0]);
    const float by1 = __ldg(&bbox[n * 4 + 1]);
    const float bx2 = __ldg(&bbox[n * 4 + 2]);
    const float by2 = __ldg(&bbox[n * 4 + 3]);
    const int   cls = __ldg(&cls_idx[n]);

    // paste box (floor) / crop box (trunc + round-half-even)
    const int x1b = (int)floorf(bx1);
    const int y1b = (int)floorf(by1);
    const int x2b = (int)floorf(bx2);
    const int y2b = (int)floorf(by2);
    const int cy1 = (int)by1;
    const int cy2 = (int)rintf(by2) + 1;

    const bool row_in_paste = (y >= max(y1b, 0)) && (y < min(y2b + 1, H_SZ));
    const bool row_in_crop  = (y >= cy1) && (y < cy2);

    if (!row_in_paste && !row_in_crop) {
        // pure zero row: 4 independent stores
        const float4 z = make_float4(0.f, 0.f, 0.f, 0.f);
        orow[lane]      = z;
        orow[lane + 32] = z;
        orow[lane + 64] = z;
        orow[lane + 96] = z;
        return;
    }

    float4 vals[4];
    #pragma unroll
    for (int j = 0; j < 4; ++j) vals[j] = make_float4(0.f, 0.f, 0.f, 0.f);

    if (row_in_paste) {
        const float bwf = (float)(x2b - x1b + 1);
        const float bhf = (float)(y2b - y1b + 1);
        const float* __restrict__ mtile =
            mask_logits + ((size_t)n * C_THING + (size_t)cls) * (M_SZ * M_SZ);

        float my = ((float)y - (float)y1b + 0.5f) * ((float)M_SZ / bhf) - 0.5f;
        my = fmaxf(my, 0.f);
        const float myf = floorf(my);
        const float fy  = my - myf;
        const int iy0 = min((int)myf,     M_SZ - 1);
        const int iy1 = min((int)myf + 1, M_SZ - 1);
        const float* __restrict__ mrow0 = mtile + iy0 * M_SZ;
        const float* __restrict__ mrow1 = mtile + iy1 * M_SZ;

        const int xlo = max(x1b, 0);
        const int xhi = min(x2b + 1, W_SZ);
        const float invbw = (float)M_SZ / bwf;

        #pragma unroll
        for (int j = 0; j < 4; ++j) {
            const int xbase = (lane + 32 * j) * 4;
            // skip float4s fully outside the box
            if (xbase + 3 < xlo || xbase >= xhi) continue;
            float* v = &vals[j].x;
            #pragma unroll
            for (int e = 0; e < 4; ++e) {
                const int x = xbase + e;
                if (x >= xlo && x < xhi) {
                    float mx = ((float)x - (float)x1b + 0.5f) * invbw - 0.5f;
                    mx = fmaxf(mx, 0.f);
                    const float mxf = floorf(mx);
                    const float fx  = mx - mxf;
                    const int ix0 = min((int)mxf,     M_SZ - 1);
                    const int ix1 = min((int)mxf + 1, M_SZ - 1);
                    const float top = mrow0[ix0] * (1.f - fx) + mrow0[ix1] * fx;
                    const float bot = mrow1[ix0] * (1.f - fx) + mrow1[ix1] * fx;
                    v[e] = (1.f - fy) * top + fy * bot;
                }
            }
        }
    }

    if (row_in_crop) {
        const int cx1 = (int)bx1;
        const int cx2 = (int)rintf(bx2) + 1;
        const float* __restrict__ srow =
            sem_seg + ((size_t)(C_STUFF + cls) * H_SZ + (size_t)y) * W_SZ;
        #pragma unroll
        for (int j = 0; j < 4; ++j) {
            const int xbase = (lane + 32 * j) * 4;
            if (xbase + 3 < cx1 || xbase >= cx2) continue;
            float* v = &vals[j].x;
            #pragma unroll
            for (int e = 0; e < 4; ++e) {
                const int x = xbase + e;
                if (x >= cx1 && x < cx2) v[e] += __ldg(&srow[x]);
            }
        }
    }

    orow[lane]      = vals[0];
    orow[lane + 32] = vals[1];
    orow[lane + 64] = vals[2];
    orow[lane + 96] = vals[3];
}

extern "C" void kernel_launch(void* const* d_in, const int* in_sizes, int n_in,
                              void* d_out, int out_size)
{
    const float* mask_logits = (const float*)d_in[0];
    const float* sem_seg     = (const float*)d_in[1];
    const float* bbox        = (const float*)d_in[2];
    const int*   cls_idx     = (const int*)d_in[3];
    float*       out         = (float*)d_out;

    const int total_rows = C_OUT * H_SZ;                 // 29952
    dim3 block(WARPS_PB * 32);                           // 256
    dim3 grid(total_rows / WARPS_PB);                    // 3744
    panoptic_all_kernel<<<grid, block>>>(mask_logits, sem_seg, bbox, cls_idx, out);
}